// round 5
// baseline (speedup 1.0000x reference)
#include <cuda_runtime.h>
#include <cuda_bf16.h>
#include <cstdint>
#include <cstddef>

#define NROWS 16384
#define KCB   8192
#define DDIM  256
#define BM    128
#define BN    64
#define NTILES (KCB / BN)            // 128
#define TILE_BYTES (BN * DDIM * 2)   // 32768 (B tile, bf16)
#define A_BYTES  (BM * DDIM * 2)     // 65536

// ---------------- static device scratch ----------------
__device__ __align__(16) unsigned int g_xB[(size_t)NROWS * 128];   // x normalized, bf16x2 row-major [row][128]
__device__ __align__(16) unsigned int g_eBn[(size_t)KCB * 128];    // embed normalized, bf16x2 row-major [n][128]
__device__ float g_flatn[(size_t)NROWS * DDIM];
__device__ float g_embn[(size_t)KCB * DDIM];
__device__ float g_denx[NROWS];
__device__ float g_dene[KCB];
__device__ int   g_cand[(size_t)NROWS * 32];
__device__ float g_cval[(size_t)NROWS * 32];
__device__ int   g_ind[NROWS];
__device__ float g_bins[KCB];
__device__ float g_esum[(size_t)KCB * DDIM];

// ---------------- PTX helpers (all plain-sm_100-legal) ----------------
#define CP_ASYNC16(dst, src) \
    asm volatile("cp.async.cg.shared.global [%0], [%1], 16;" :: "r"(dst), "l"(src))
#define CP_COMMIT() asm volatile("cp.async.commit_group;" ::: "memory")
#define CP_WAIT0()  asm volatile("cp.async.wait_group 0;" ::: "memory")
#define CP_WAIT1()  asm volatile("cp.async.wait_group 1;" ::: "memory")

__device__ __forceinline__ void ldsm4(uint32_t addr, uint32_t& r0, uint32_t& r1,
                                      uint32_t& r2, uint32_t& r3) {
    asm volatile("ldmatrix.sync.aligned.m8n8.x4.shared.b16 {%0,%1,%2,%3}, [%4];"
                 : "=r"(r0), "=r"(r1), "=r"(r2), "=r"(r3) : "r"(addr));
}

__device__ __forceinline__ void mma16816(float* c, const uint32_t* a, const uint32_t* b) {
    asm volatile("mma.sync.aligned.m16n8k16.row.col.f32.bf16.bf16.f32 "
                 "{%0,%1,%2,%3}, {%4,%5,%6,%7}, {%8,%9}, {%0,%1,%2,%3};"
                 : "+f"(c[0]), "+f"(c[1]), "+f"(c[2]), "+f"(c[3])
                 : "r"(a[0]), "r"(a[1]), "r"(a[2]), "r"(a[3]), "r"(b[0]), "r"(b[1]));
}

// ---------------- K0: normalize x rows -> g_flatn (fp32) + g_xB (bf16x2) ----------------
__global__ void k_norm_x(const float* __restrict__ x) {
    int w = (blockIdx.x * blockDim.x + threadIdx.x) >> 5;
    int lane = threadIdx.x & 31;
    if (w >= NROWS) return;
    const float2* x2 = (const float2*)x;
    float2 v[4];
    float s = 0.f;
#pragma unroll
    for (int i = 0; i < 4; i++) {
        v[i] = x2[(size_t)w * 128 + i * 32 + lane];
        s += v[i].x * v[i].x + v[i].y * v[i].y;
    }
#pragma unroll
    for (int off = 16; off >= 1; off >>= 1) s += __shfl_xor_sync(0xffffffffu, s, off);
    float den = fmaxf(__fsqrt_rn(s), 1e-12f);
#pragma unroll
    for (int i = 0; i < 4; i++) {
        int d2 = i * 32 + lane;
        float2 o;
        o.x = __fdiv_rn(v[i].x, den);
        o.y = __fdiv_rn(v[i].y, den);
        ((float2*)g_flatn)[(size_t)w * 128 + d2] = o;
        unsigned int u = ((unsigned int)__bfloat16_as_ushort(__float2bfloat16_rn(o.y)) << 16)
                       |  (unsigned int)__bfloat16_as_ushort(__float2bfloat16_rn(o.x));
        g_xB[(size_t)w * 128 + d2] = u;
    }
    if (lane == 0) g_denx[w] = den;
}

// ---------------- K1: normalize embed rows -> g_embn (fp32) + g_eBn (bf16x2) ----------------
__global__ void k_norm_e(const float* __restrict__ e) {
    int w = (blockIdx.x * blockDim.x + threadIdx.x) >> 5;
    int lane = threadIdx.x & 31;
    if (w >= KCB) return;
    const float2* e2 = (const float2*)e;
    float2 v[4];
    float s = 0.f;
#pragma unroll
    for (int i = 0; i < 4; i++) {
        v[i] = e2[(size_t)w * 128 + i * 32 + lane];
        s += v[i].x * v[i].x + v[i].y * v[i].y;
    }
#pragma unroll
    for (int off = 16; off >= 1; off >>= 1) s += __shfl_xor_sync(0xffffffffu, s, off);
    float den = fmaxf(__fsqrt_rn(s), 1e-12f);
#pragma unroll
    for (int i = 0; i < 4; i++) {
        int d2 = i * 32 + lane;
        float2 o;
        o.x = __fdiv_rn(v[i].x, den);
        o.y = __fdiv_rn(v[i].y, den);
        ((float2*)g_embn)[(size_t)w * 128 + d2] = o;
        unsigned int u = ((unsigned int)__bfloat16_as_ushort(__float2bfloat16_rn(o.y)) << 16)
                       |  (unsigned int)__bfloat16_as_ushort(__float2bfloat16_rn(o.x));
        g_eBn[(size_t)w * 128 + d2] = u;
    }
    if (lane == 0) g_dene[w] = den;
}

// ---------------- K3: zero accumulators ----------------
__global__ void k_zero() {
    int i = blockIdx.x * blockDim.x + threadIdx.x;
    for (int j = i; j < KCB * DDIM; j += gridDim.x * blockDim.x) g_esum[j] = 0.f;
    if (i < KCB) g_bins[i] = 0.f;
}

// ---------------- K2: HMMA bf16 GEMM, A register-resident, per-thread dual top-2 ----------------
// 256 threads, 8 warps (4 row-slabs x 2 col-halves), warp tile 32x32, BN=64.
// smem: 64KB — A staging, then aliased as B0 (32KB) | B1 (32KB).
__global__ void __launch_bounds__(256, 1) k_gemm_top2() {
    extern __shared__ unsigned char smem[];
    uint32_t sb = (uint32_t)__cvta_generic_to_shared(smem);
    uint32_t sBbuf0 = sb;
    uint32_t sBbuf1 = sb + TILE_BYTES;

    int tid = threadIdx.x;
    int lane = tid & 31;
    int wid = tid >> 5;
    int wm = wid >> 1;          // 0..3 (row 32-slab)
    int wn = wid & 1;           // 0..1 (col 32-half of BN=64)
    int rowblk = blockIdx.x * BM;

    // ---- stage A tile into smem (swizzled) ----
    {
        const char* srcA = (const char*)g_xB + (size_t)rowblk * 512;
#pragma unroll
        for (int q = 0; q < 16; q++) {
            int idx = tid + q * 256;
            int r = idx >> 5, c = idx & 31;
            uint32_t doff = (uint32_t)r * 512 + (uint32_t)((c ^ (r & 7)) << 4);
            CP_ASYNC16(sb + doff, srcA + (size_t)idx * 16);
        }
        CP_COMMIT();
        CP_WAIT0();
    }
    __syncthreads();

    // ---- load ALL A fragments into registers: afr[ks][mt][4] flattened ----
    uint32_t afr[128];
    {
        int swzA = lane & 7;
        int khalfA = lane >> 4;
        uint32_t aRowB[2];
#pragma unroll
        for (int mt = 0; mt < 2; mt++)
            aRowB[mt] = sb + (uint32_t)(wm * 32 + mt * 16 + (lane & 15)) * 512;
#pragma unroll
        for (int ks = 0; ks < 16; ks++) {
            uint32_t offA = (uint32_t)(((ks * 2 + khalfA) ^ swzA) << 4);
#pragma unroll
            for (int mt = 0; mt < 2; mt++) {
                int base = (ks * 2 + mt) * 4;
                ldsm4(aRowB[mt] + offA, afr[base + 0], afr[base + 1], afr[base + 2], afr[base + 3]);
            }
        }
    }
    __syncthreads();   // all warps done reading A staging before B overwrites it

    // ---- prefetch B tile 0 into buf0 ----
    {
        const char* srcB = (const char*)g_eBn;
#pragma unroll
        for (int q = 0; q < 8; q++) {
            int idx = tid + q * 256;
            int r = idx >> 5, c = idx & 31;
            uint32_t doff = (uint32_t)r * 512 + (uint32_t)((c ^ (r & 7)) << 4);
            CP_ASYNC16(sBbuf0 + doff, srcB + (size_t)idx * 16);
        }
        CP_COMMIT();
    }

    // ---- B fragment addressing ----
    int swzB = lane & 7;
    int khalfB = (lane >> 3) & 1;
    uint32_t bRowOff[2];
#pragma unroll
    for (int ntp = 0; ntp < 2; ntp++)
        bRowOff[ntp] = (uint32_t)(wn * 32 + ntp * 16 + (lane >> 4) * 8 + (lane & 7)) * 512;

    // ---- per-thread dual top-2: index = lr*2 + half, lr = mt*2 + h ----
    float v1[8], v2[8];
    int   i1[8], i2[8];
#pragma unroll
    for (int s = 0; s < 8; s++) { v1[s] = -3.4e38f; v2[s] = -3.4e38f; i1[s] = 0; i2[s] = 0; }

    for (int t = 0; t < NTILES; t++) {
        // prefetch tile t+1 into buffer (t+1)&1
        if (t + 1 < NTILES) {
            const char* srcB = (const char*)g_eBn + (size_t)(t + 1) * TILE_BYTES;
            uint32_t dst = ((t + 1) & 1) ? sBbuf1 : sBbuf0;
#pragma unroll
            for (int q = 0; q < 8; q++) {
                int idx = tid + q * 256;
                int r = idx >> 5, c = idx & 31;
                uint32_t doff = (uint32_t)r * 512 + (uint32_t)((c ^ (r & 7)) << 4);
                CP_ASYNC16(dst + doff, srcB + (size_t)idx * 16);
            }
            CP_COMMIT();
            CP_WAIT1();     // tile t's group complete; t+1's may be in flight
        } else {
            CP_WAIT0();
        }
        __syncthreads();

        uint32_t sB = (t & 1) ? sBbuf1 : sBbuf0;

        float acc[2][4][4];
#pragma unroll
        for (int mt = 0; mt < 2; mt++)
#pragma unroll
            for (int nt = 0; nt < 4; nt++)
#pragma unroll
                for (int cc = 0; cc < 4; cc++) acc[mt][nt][cc] = 0.f;

        // double-buffered B fragments; A is in registers
        uint32_t b[2][4][2];
        {
            uint32_t offB = (uint32_t)((khalfB ^ swzB) << 4);
#pragma unroll
            for (int ntp = 0; ntp < 2; ntp++) {
                uint32_t r0, r1, r2, r3;
                ldsm4(sB + bRowOff[ntp] + offB, r0, r1, r2, r3);
                b[0][ntp * 2][0] = r0; b[0][ntp * 2][1] = r1;
                b[0][ntp * 2 + 1][0] = r2; b[0][ntp * 2 + 1][1] = r3;
            }
        }

#pragma unroll
        for (int ks = 0; ks < 16; ks++) {
            int cur = ks & 1, nxt = cur ^ 1;
            if (ks < 15) {
                uint32_t offB = (uint32_t)((((ks + 1) * 2 + khalfB) ^ swzB) << 4);
#pragma unroll
                for (int ntp = 0; ntp < 2; ntp++) {
                    uint32_t r0, r1, r2, r3;
                    ldsm4(sB + bRowOff[ntp] + offB, r0, r1, r2, r3);
                    b[nxt][ntp * 2][0] = r0; b[nxt][ntp * 2][1] = r1;
                    b[nxt][ntp * 2 + 1][0] = r2; b[nxt][ntp * 2 + 1][1] = r3;
                }
            }
#pragma unroll
            for (int mt = 0; mt < 2; mt++)
#pragma unroll
                for (int nt = 0; nt < 4; nt++)
                    mma16816(acc[mt][nt], &afr[(ks * 2 + mt) * 4], b[cur][nt]);
        }

        // epilogue: dual top-2 update (separate bucket per column half)
        int colq = t * BN + wn * 32 + 2 * (lane & 3);
#pragma unroll
        for (int mt = 0; mt < 2; mt++) {
#pragma unroll
            for (int h = 0; h < 2; h++) {
                int lr = mt * 2 + h;
#pragma unroll
                for (int half = 0; half < 2; half++) {
                    int sidx = lr * 2 + half;
                    float va0 = acc[mt][half * 2 + 0][h * 2 + 0];
                    float vb0 = acc[mt][half * 2 + 0][h * 2 + 1];
                    float va1 = acc[mt][half * 2 + 1][h * 2 + 0];
                    float vb1 = acc[mt][half * 2 + 1][h * 2 + 1];
                    float mx = fmaxf(fmaxf(va0, vb0), fmaxf(va1, vb1));
                    if (mx > v2[sidx]) {
                        int c0 = colq + (half * 2 + 0) * 8;
                        int c1 = colq + (half * 2 + 1) * 8;
                        if (va0 > v1[sidx]) { v2[sidx] = v1[sidx]; i2[sidx] = i1[sidx]; v1[sidx] = va0; i1[sidx] = c0; }
                        else if (va0 > v2[sidx]) { v2[sidx] = va0; i2[sidx] = c0; }
                        if (vb0 > v1[sidx]) { v2[sidx] = v1[sidx]; i2[sidx] = i1[sidx]; v1[sidx] = vb0; i1[sidx] = c0 + 1; }
                        else if (vb0 > v2[sidx]) { v2[sidx] = vb0; i2[sidx] = c0 + 1; }
                        if (va1 > v1[sidx]) { v2[sidx] = v1[sidx]; i2[sidx] = i1[sidx]; v1[sidx] = va1; i1[sidx] = c1; }
                        else if (va1 > v2[sidx]) { v2[sidx] = va1; i2[sidx] = c1; }
                        if (vb1 > v1[sidx]) { v2[sidx] = v1[sidx]; i2[sidx] = i1[sidx]; v1[sidx] = vb1; i1[sidx] = c1 + 1; }
                        else if (vb1 > v2[sidx]) { v2[sidx] = vb1; i2[sidx] = c1 + 1; }
                    }
                }
            }
        }
        __syncthreads();   // everyone done reading sB before next prefetch overwrites it
    }

    // write candidates: each row gets 32 slots = 16 buckets x 2
#pragma unroll
    for (int mt = 0; mt < 2; mt++) {
#pragma unroll
        for (int h = 0; h < 2; h++) {
            int lr = mt * 2 + h;
            int row = rowblk + wm * 32 + mt * 16 + (lane >> 2) + h * 8;
#pragma unroll
            for (int half = 0; half < 2; half++) {
                int sidx = lr * 2 + half;
                int slot = ((wn * 2 + half) * 4 + (lane & 3)) * 2;
                g_cand[(size_t)row * 32 + slot]     = i1[sidx];
                g_cand[(size_t)row * 32 + slot + 1] = i2[sidx];
                g_cval[(size_t)row * 32 + slot]     = v1[sidx];
                g_cval[(size_t)row * 32 + slot + 1] = v2[sidx];
            }
        }
    }
}

// ---------------- K2b: margin-gated exact fp32 rescore ----------------
__global__ void k_rescore() {
    int r = blockIdx.x * 8 + (threadIdx.x >> 5);
    int lane = threadIdx.x & 31;
    if (r >= NROWS) return;
    const float4* fr = (const float4*)(g_flatn + (size_t)r * DDIM);
    float4 fa = fr[lane * 2], fb = fr[lane * 2 + 1];

    float cv = g_cval[(size_t)r * 32 + lane];
    int   ci = g_cand[(size_t)r * 32 + lane];
    float wmax = cv;
#pragma unroll
    for (int off = 16; off >= 1; off >>= 1) wmax = fmaxf(wmax, __shfl_xor_sync(0xffffffffu, wmax, off));
    unsigned m = __ballot_sync(0xffffffffu, cv >= wmax - 2.5e-3f);

    float best = -3.4e38f;
    int besti = 0x7fffffff;
    while (m) {
        int b = __ffs(m) - 1;
        m &= m - 1;
        int cj = __shfl_sync(0xffffffffu, ci, b);
        const float4* er = (const float4*)(g_embn + (size_t)cj * DDIM);
        float4 ea = er[lane * 2], eb = er[lane * 2 + 1];
        float s = fa.x * ea.x + fa.y * ea.y + fa.z * ea.z + fa.w * ea.w
                + fb.x * eb.x + fb.y * eb.y + fb.z * eb.z + fb.w * eb.w;
#pragma unroll
        for (int off = 16; off >= 1; off >>= 1) s += __shfl_xor_sync(0xffffffffu, s, off);
        if (s > best || (s == best && cj < besti)) { best = s; besti = cj; }
    }
    if (lane == 0) g_ind[r] = besti;
}

// ---------------- K4: quantize gather + index out + segment-sum scatter ----------------
__global__ void k_scatter(const float* __restrict__ x, const float* __restrict__ embed,
                          float* __restrict__ out_q, float* __restrict__ out_ind) {
    int n = blockIdx.x;
    int t = threadIdx.x;
    int ind = g_ind[n];
    float den = g_denx[n];
    float fl = __fdiv_rn(x[(size_t)n * DDIM + t], den);
    atomicAdd(&g_esum[(size_t)ind * DDIM + t], fl);
    out_q[(size_t)n * DDIM + t] = embed[(size_t)ind * DDIM + t];
    if (t == 0) {
        atomicAdd(&g_bins[ind], 1.0f);
        out_ind[n] = (float)ind;
    }
}

// ---------------- K5: EMA finalize -> embed_new ----------------
__global__ void k_final(const float* __restrict__ embed, float* __restrict__ out_e) {
    int w = (blockIdx.x * blockDim.x + threadIdx.x) >> 5;
    int lane = threadIdx.x & 31;
    if (w >= KCB) return;
    float b = g_bins[w];
    bool zero = (b == 0.0f);
    float bs = zero ? 1.0f : b;
    float m[8];
    float s = 0.f;
#pragma unroll
    for (int i = 0; i < 8; i++) {
        int d = i * 32 + lane;
        m[i] = __fdiv_rn(g_esum[(size_t)w * DDIM + d], bs);
        s += m[i] * m[i];
    }
#pragma unroll
    for (int off = 16; off >= 1; off >>= 1) s += __shfl_xor_sync(0xffffffffu, s, off);
    float nrm = fmaxf(__fsqrt_rn(s), 1e-12f);
    float dene = g_dene[w];
#pragma unroll
    for (int i = 0; i < 8; i++) {
        int d = i * 32 + lane;
        float ev = embed[(size_t)w * DDIM + d];
        float en = zero ? __fdiv_rn(ev, dene) : __fdiv_rn(m[i], nrm);
        out_e[(size_t)w * DDIM + d] = ev * 0.8f + en * 0.2f;
    }
}

// ---------------- launcher ----------------
extern "C" void kernel_launch(void* const* d_in, const int* in_sizes, int n_in,
                              void* d_out, int out_size) {
    const float* x     = (const float*)d_in[0];
    const float* embed = (const float*)d_in[1];
    float* out     = (float*)d_out;
    float* out_q   = out;                          // [16384, 256]
    float* out_ind = out + (size_t)NROWS * DDIM;   // [16384]
    float* out_e   = out_ind + NROWS;              // [8192, 256]

    (void)in_sizes; (void)n_in; (void)out_size;

    const int smem_bytes = A_BYTES;   // 64 KB (A staging, aliased as 2x32KB B buffers)
    cudaFuncSetAttribute(k_gemm_top2, cudaFuncAttributeMaxDynamicSharedMemorySize, smem_bytes);

    k_norm_x<<<NROWS / 8, 256>>>(x);
    k_norm_e<<<KCB / 8, 256>>>(embed);
    k_zero<<<2048, 256>>>();
    k_gemm_top2<<<NROWS / BM, 256, smem_bytes>>>();
    k_rescore<<<NROWS / 8, 256>>>();
    k_scatter<<<NROWS, 256>>>(x, embed, out_q, out_ind);
    k_final<<<KCB / 8, 256>>>(embed, out_e);
}

// round 6
// speedup vs baseline: 1.2206x; 1.2206x over previous
#include <cuda_runtime.h>
#include <cuda_bf16.h>
#include <cstdint>
#include <cstddef>

#define NROWS 16384
#define KCB   8192
#define DDIM  256
#define BM    128
#define BNBLK 256                       // col-block per pipeline pass
#define NBLKS (KCB / BNBLK)             // 32
#define NSTEPS (NBLKS * 2)              // 64 (2 k-stages per block)
#define STAGE_BYTES (BNBLK * 128 * 2)   // 65536: 256 rows x 128 k x bf16
#define A_BYTES  (BM * DDIM * 2)        // 65536

// ---------------- static device scratch ----------------
__device__ __align__(16) unsigned int g_xB[(size_t)NROWS * 128];    // x normalized, bf16x2 row-major [row][128]
__device__ __align__(16) unsigned char g_eBs[(size_t)KCB * 512];    // embed normalized bf16, stage-major pre-swizzled
__device__ float g_flatn[(size_t)NROWS * DDIM];
__device__ float g_embn[(size_t)KCB * DDIM];
__device__ float g_denx[NROWS];
__device__ float g_dene[KCB];
__device__ int   g_cand[(size_t)NROWS * 32];
__device__ float g_cval[(size_t)NROWS * 32];
__device__ int   g_ind[NROWS];
__device__ float g_bins[KCB];
__device__ float g_esum[(size_t)KCB * DDIM];

// ---------------- PTX helpers (all plain-sm_100-legal) ----------------
#define CP_ASYNC16(dst, src) \
    asm volatile("cp.async.cg.shared.global [%0], [%1], 16;" :: "r"(dst), "l"(src))
#define CP_COMMIT() asm volatile("cp.async.commit_group;" ::: "memory")
#define CP_WAIT0()  asm volatile("cp.async.wait_group 0;" ::: "memory")
#define CP_WAIT1()  asm volatile("cp.async.wait_group 1;" ::: "memory")

__device__ __forceinline__ void ldsm4(uint32_t addr, uint32_t& r0, uint32_t& r1,
                                      uint32_t& r2, uint32_t& r3) {
    asm volatile("ldmatrix.sync.aligned.m8n8.x4.shared.b16 {%0,%1,%2,%3}, [%4];"
                 : "=r"(r0), "=r"(r1), "=r"(r2), "=r"(r3) : "r"(addr));
}

__device__ __forceinline__ void mma16816(float* c, const uint32_t* a, const uint32_t* b) {
    asm volatile("mma.sync.aligned.m16n8k16.row.col.f32.bf16.bf16.f32 "
                 "{%0,%1,%2,%3}, {%4,%5,%6,%7}, {%8,%9}, {%0,%1,%2,%3};"
                 : "+f"(c[0]), "+f"(c[1]), "+f"(c[2]), "+f"(c[3])
                 : "r"(a[0]), "r"(a[1]), "r"(a[2]), "r"(a[3]), "r"(b[0]), "r"(b[1]));
}

// ---------------- K0: normalize x rows -> g_flatn (fp32) + g_xB (bf16x2) ----------------
__global__ void k_norm_x(const float* __restrict__ x) {
    int w = (blockIdx.x * blockDim.x + threadIdx.x) >> 5;
    int lane = threadIdx.x & 31;
    if (w >= NROWS) return;
    const float2* x2 = (const float2*)x;
    float2 v[4];
    float s = 0.f;
#pragma unroll
    for (int i = 0; i < 4; i++) {
        v[i] = x2[(size_t)w * 128 + i * 32 + lane];
        s += v[i].x * v[i].x + v[i].y * v[i].y;
    }
#pragma unroll
    for (int off = 16; off >= 1; off >>= 1) s += __shfl_xor_sync(0xffffffffu, s, off);
    float den = fmaxf(__fsqrt_rn(s), 1e-12f);
#pragma unroll
    for (int i = 0; i < 4; i++) {
        int d2 = i * 32 + lane;
        float2 o;
        o.x = __fdiv_rn(v[i].x, den);
        o.y = __fdiv_rn(v[i].y, den);
        ((float2*)g_flatn)[(size_t)w * 128 + d2] = o;
        unsigned int u = ((unsigned int)__bfloat16_as_ushort(__float2bfloat16_rn(o.y)) << 16)
                       |  (unsigned int)__bfloat16_as_ushort(__float2bfloat16_rn(o.x));
        g_xB[(size_t)w * 128 + d2] = u;
    }
    if (lane == 0) g_denx[w] = den;
}

// ---------------- K1: normalize embed -> g_embn (fp32) + g_eBs (stage-major swizzled bf16) ----------------
// g_eBs layout: [block 32][stage 2][row 256][256B], chunk c (16B) stored at (c ^ (row&7))*16 + intra
__global__ void k_norm_e(const float* __restrict__ e) {
    int w = (blockIdx.x * blockDim.x + threadIdx.x) >> 5;
    int lane = threadIdx.x & 31;
    if (w >= KCB) return;
    const float2* e2 = (const float2*)e;
    float2 v[4];
    float s = 0.f;
#pragma unroll
    for (int i = 0; i < 4; i++) {
        v[i] = e2[(size_t)w * 128 + i * 32 + lane];
        s += v[i].x * v[i].x + v[i].y * v[i].y;
    }
#pragma unroll
    for (int off = 16; off >= 1; off >>= 1) s += __shfl_xor_sync(0xffffffffu, s, off);
    float den = fmaxf(__fsqrt_rn(s), 1e-12f);

    int blk = w >> 8, row = w & 255;
    size_t base = (size_t)blk * 131072 + (size_t)row * 256;
#pragma unroll
    for (int i = 0; i < 4; i++) {
        int d2 = i * 32 + lane;                 // pair index 0..127
        float2 o;
        o.x = __fdiv_rn(v[i].x, den);
        o.y = __fdiv_rn(v[i].y, den);
        ((float2*)g_embn)[(size_t)w * 128 + d2] = o;
        unsigned int u = ((unsigned int)__bfloat16_as_ushort(__float2bfloat16_rn(o.y)) << 16)
                       |  (unsigned int)__bfloat16_as_ushort(__float2bfloat16_rn(o.x));
        int stage = d2 >> 6;                    // k-half
        int d2s = d2 & 63;
        int c = d2s >> 2;                       // 16B chunk 0..15
        int intra = (d2s & 3) * 4;
        *(unsigned int*)(g_eBs + base + (size_t)stage * STAGE_BYTES
                         + (size_t)((c ^ (row & 7)) << 4) + intra) = u;
    }
    if (lane == 0) g_dene[w] = den;
}

// ---------------- K3: zero accumulators ----------------
__global__ void k_zero() {
    int i = blockIdx.x * blockDim.x + threadIdx.x;
    for (int j = i; j < KCB * DDIM; j += gridDim.x * blockDim.x) g_esum[j] = 0.f;
    if (i < KCB) g_bins[i] = 0.f;
}

// ---------------- K2: HMMA bf16 GEMM, 16 warps, warp tile 32x64, k-staged ----------------
// smem: A (64KB, swizzled 512B rows) | Bbuf0 (64KB) | Bbuf1 (64KB)
__global__ void __launch_bounds__(512, 1) k_gemm_top2() {
    extern __shared__ unsigned char smem[];
    uint32_t sb = (uint32_t)__cvta_generic_to_shared(smem);
    uint32_t sA = sb;
    uint32_t sBbuf0 = sb + A_BYTES;
    uint32_t sBbuf1 = sb + A_BYTES + STAGE_BYTES;

    int tid = threadIdx.x;
    int lane = tid & 31;
    int wid = tid >> 5;
    int wm = wid >> 2;          // 0..3 (row 32-slab)
    int wn = wid & 3;           // 0..3 (col 64-slice of 256)
    int rowblk = blockIdx.x * BM;

    // ---- stage A tile into smem (swizzled, 512B rows) ----
    {
        const char* srcA = (const char*)g_xB + (size_t)rowblk * 512;
#pragma unroll
        for (int q = 0; q < 8; q++) {
            int idx = tid + q * 512;
            int r = idx >> 5, c = idx & 31;
            uint32_t doff = (uint32_t)r * 512 + (uint32_t)((c ^ (r & 7)) << 4);
            CP_ASYNC16(sA + doff, srcA + (size_t)idx * 16);
        }
        CP_COMMIT();
    }
    // ---- prefetch B step 0 (linear: pre-swizzled in gmem) ----
    {
        const char* srcB = (const char*)g_eBs;
#pragma unroll
        for (int q = 0; q < 8; q++) {
            int idx = tid + q * 512;
            CP_ASYNC16(sBbuf0 + (uint32_t)idx * 16, srcB + (size_t)idx * 16);
        }
        CP_COMMIT();
    }

    // ---- fragment addressing ----
    int swz = lane & 7;
    int khalfA = lane >> 4;
    uint32_t aRowB[2];
#pragma unroll
    for (int mt = 0; mt < 2; mt++)
        aRowB[mt] = sA + (uint32_t)(wm * 32 + mt * 16 + (lane & 15)) * 512;
    int khalfB = (lane >> 3) & 1;
    uint32_t bRowOff[4];
#pragma unroll
    for (int ntp = 0; ntp < 4; ntp++)
        bRowOff[ntp] = (uint32_t)(wn * 64 + ntp * 16 + (lane >> 4) * 8 + (lane & 7)) * 256;

    // ---- per-thread top-2 per row (4 rows: mt*2 + h) ----
    float v1[4], v2[4];
    int   i1[4], i2[4];
#pragma unroll
    for (int s = 0; s < 4; s++) { v1[s] = -3.4e38f; v2[s] = -3.4e38f; i1[s] = 0; i2[s] = 0; }

    float acc[2][8][4];

    for (int p = 0; p < NSTEPS; p++) {
        int stage = p & 1;
        // prefetch step p+1
        if (p + 1 < NSTEPS) {
            const char* srcB = (const char*)g_eBs + (size_t)(p + 1) * STAGE_BYTES;
            uint32_t dst = ((p + 1) & 1) ? sBbuf1 : sBbuf0;
#pragma unroll
            for (int q = 0; q < 8; q++) {
                int idx = tid + q * 512;
                CP_ASYNC16(dst + (uint32_t)idx * 16, srcB + (size_t)idx * 16);
            }
            CP_COMMIT();
            CP_WAIT1();
        } else {
            CP_WAIT0();
        }
        __syncthreads();

        uint32_t sB = (p & 1) ? sBbuf1 : sBbuf0;

        if (stage == 0) {
#pragma unroll
            for (int mt = 0; mt < 2; mt++)
#pragma unroll
                for (int nt = 0; nt < 8; nt++)
#pragma unroll
                    for (int cc = 0; cc < 4; cc++) acc[mt][nt][cc] = 0.f;
        }

#pragma unroll
        for (int ks = 0; ks < 8; ks++) {
            // A fragments: global chunk = stage*16 + ks*2 + khalfA
            uint32_t a[2][4];
            uint32_t offA = (uint32_t)(((stage * 16 + ks * 2 + khalfA) ^ swz) << 4);
#pragma unroll
            for (int mt = 0; mt < 2; mt++)
                ldsm4(aRowB[mt] + offA, a[mt][0], a[mt][1], a[mt][2], a[mt][3]);
            // B fragments: chunk = ks*2 + khalfB within stage
            uint32_t b[8][2];
            uint32_t offB = (uint32_t)(((ks * 2 + khalfB) ^ swz) << 4);
#pragma unroll
            for (int ntp = 0; ntp < 4; ntp++) {
                uint32_t r0, r1, r2, r3;
                ldsm4(sB + bRowOff[ntp] + offB, r0, r1, r2, r3);
                b[ntp * 2][0] = r0; b[ntp * 2][1] = r1;
                b[ntp * 2 + 1][0] = r2; b[ntp * 2 + 1][1] = r3;
            }
#pragma unroll
            for (int mt = 0; mt < 2; mt++)
#pragma unroll
                for (int nt = 0; nt < 8; nt++)
                    mma16816(acc[mt][nt], a[mt], b[nt]);
        }

        if (stage == 1) {
            // epilogue: top-2 update over the 256-col block (k complete)
            int colq = (p >> 1) * BNBLK + wn * 64 + 2 * (lane & 3);
#pragma unroll
            for (int mt = 0; mt < 2; mt++) {
#pragma unroll
                for (int h = 0; h < 2; h++) {
                    int lr = mt * 2 + h;
#pragma unroll
                    for (int nt = 0; nt < 8; nt++) {
                        float va = acc[mt][nt][h * 2 + 0];
                        float vb = acc[mt][nt][h * 2 + 1];
                        if (fmaxf(va, vb) > v2[lr]) {
                            int c0 = colq + nt * 8;
                            if (va > v1[lr]) { v2[lr] = v1[lr]; i2[lr] = i1[lr]; v1[lr] = va; i1[lr] = c0; }
                            else if (va > v2[lr]) { v2[lr] = va; i2[lr] = c0; }
                            if (vb > v1[lr]) { v2[lr] = v1[lr]; i2[lr] = i1[lr]; v1[lr] = vb; i1[lr] = c0 + 1; }
                            else if (vb > v2[lr]) { v2[lr] = vb; i2[lr] = c0 + 1; }
                        }
                    }
                }
            }
        }
        __syncthreads();   // done reading sB before prefetch of p+2 overwrites it
    }

    // write candidates: each row gets 32 slots = 16 buckets x 2
#pragma unroll
    for (int mt = 0; mt < 2; mt++) {
#pragma unroll
        for (int h = 0; h < 2; h++) {
            int lr = mt * 2 + h;
            int row = rowblk + wm * 32 + mt * 16 + (lane >> 2) + h * 8;
            int slot = (wn * 4 + (lane & 3)) * 2;
            g_cand[(size_t)row * 32 + slot]     = i1[lr];
            g_cand[(size_t)row * 32 + slot + 1] = i2[lr];
            g_cval[(size_t)row * 32 + slot]     = v1[lr];
            g_cval[(size_t)row * 32 + slot + 1] = v2[lr];
        }
    }
}

// ---------------- K2b: margin-gated exact fp32 rescore ----------------
__global__ void k_rescore() {
    int r = blockIdx.x * 8 + (threadIdx.x >> 5);
    int lane = threadIdx.x & 31;
    if (r >= NROWS) return;
    const float4* fr = (const float4*)(g_flatn + (size_t)r * DDIM);
    float4 fa = fr[lane * 2], fb = fr[lane * 2 + 1];

    float cv = g_cval[(size_t)r * 32 + lane];
    int   ci = g_cand[(size_t)r * 32 + lane];
    float wmax = cv;
#pragma unroll
    for (int off = 16; off >= 1; off >>= 1) wmax = fmaxf(wmax, __shfl_xor_sync(0xffffffffu, wmax, off));
    unsigned m = __ballot_sync(0xffffffffu, cv >= wmax - 2.5e-3f);

    float best = -3.4e38f;
    int besti = 0x7fffffff;
    while (m) {
        int b = __ffs(m) - 1;
        m &= m - 1;
        int cj = __shfl_sync(0xffffffffu, ci, b);
        const float4* er = (const float4*)(g_embn + (size_t)cj * DDIM);
        float4 ea = er[lane * 2], eb = er[lane * 2 + 1];
        float s = fa.x * ea.x + fa.y * ea.y + fa.z * ea.z + fa.w * ea.w
                + fb.x * eb.x + fb.y * eb.y + fb.z * eb.z + fb.w * eb.w;
#pragma unroll
        for (int off = 16; off >= 1; off >>= 1) s += __shfl_xor_sync(0xffffffffu, s, off);
        if (s > best || (s == best && cj < besti)) { best = s; besti = cj; }
    }
    if (lane == 0) g_ind[r] = besti;
}

// ---------------- K4: quantize gather + index out + segment-sum scatter ----------------
__global__ void k_scatter(const float* __restrict__ x, const float* __restrict__ embed,
                          float* __restrict__ out_q, float* __restrict__ out_ind) {
    int n = blockIdx.x;
    int t = threadIdx.x;
    int ind = g_ind[n];
    float den = g_denx[n];
    float fl = __fdiv_rn(x[(size_t)n * DDIM + t], den);
    atomicAdd(&g_esum[(size_t)ind * DDIM + t], fl);
    out_q[(size_t)n * DDIM + t] = embed[(size_t)ind * DDIM + t];
    if (t == 0) {
        atomicAdd(&g_bins[ind], 1.0f);
        out_ind[n] = (float)ind;
    }
}

// ---------------- K5: EMA finalize -> embed_new ----------------
__global__ void k_final(const float* __restrict__ embed, float* __restrict__ out_e) {
    int w = (blockIdx.x * blockDim.x + threadIdx.x) >> 5;
    int lane = threadIdx.x & 31;
    if (w >= KCB) return;
    float b = g_bins[w];
    bool zero = (b == 0.0f);
    float bs = zero ? 1.0f : b;
    float m[8];
    float s = 0.f;
#pragma unroll
    for (int i = 0; i < 8; i++) {
        int d = i * 32 + lane;
        m[i] = __fdiv_rn(g_esum[(size_t)w * DDIM + d], bs);
        s += m[i] * m[i];
    }
#pragma unroll
    for (int off = 16; off >= 1; off >>= 1) s += __shfl_xor_sync(0xffffffffu, s, off);
    float nrm = fmaxf(__fsqrt_rn(s), 1e-12f);
    float dene = g_dene[w];
#pragma unroll
    for (int i = 0; i < 8; i++) {
        int d = i * 32 + lane;
        float ev = embed[(size_t)w * DDIM + d];
        float en = zero ? __fdiv_rn(ev, dene) : __fdiv_rn(m[i], nrm);
        out_e[(size_t)w * DDIM + d] = ev * 0.8f + en * 0.2f;
    }
}

// ---------------- launcher ----------------
extern "C" void kernel_launch(void* const* d_in, const int* in_sizes, int n_in,
                              void* d_out, int out_size) {
    const float* x     = (const float*)d_in[0];
    const float* embed = (const float*)d_in[1];
    float* out     = (float*)d_out;
    float* out_q   = out;                          // [16384, 256]
    float* out_ind = out + (size_t)NROWS * DDIM;   // [16384]
    float* out_e   = out_ind + NROWS;              // [8192, 256]

    (void)in_sizes; (void)n_in; (void)out_size;

    const int smem_bytes = A_BYTES + 2 * STAGE_BYTES;   // 192 KB
    cudaFuncSetAttribute(k_gemm_top2, cudaFuncAttributeMaxDynamicSharedMemorySize, smem_bytes);

    k_norm_x<<<NROWS / 8, 256>>>(x);
    k_norm_e<<<KCB / 8, 256>>>(embed);
    k_zero<<<2048, 256>>>();
    k_gemm_top2<<<NROWS / BM, 512, smem_bytes>>>();
    k_rescore<<<NROWS / 8, 256>>>();
    k_scatter<<<NROWS, 256>>>(x, embed, out_q, out_ind);
    k_final<<<KCB / 8, 256>>>(embed, out_e);
}

// round 8
// speedup vs baseline: 1.2847x; 1.0526x over previous
#include <cuda_runtime.h>
#include <cuda_bf16.h>
#include <cstdint>
#include <cstddef>

#define NROWS 16384
#define KCB   8192
#define DDIM  256
#define BM    128
#define BNBLK 256                       // col-block per acc lifetime
#define NBLKS (KCB / BNBLK)             // 32
#define NSTEPS (NBLKS * 2)              // 64 (2 k-stages per block)
#define STAGE_BYTES 65536               // full 256-row x 128-k stage in gmem image
#define SLICE_BYTES 16384               // per-group 64-row x 128-k slice
#define A_BYTES  (BM * DDIM * 2)        // 65536

// ---------------- static device scratch ----------------
__device__ __align__(16) unsigned int g_xB[(size_t)NROWS * 128];    // x normalized, bf16x2 row-major [row][128]
__device__ __align__(16) unsigned char g_eBs[(size_t)KCB * 512];    // embed normalized bf16, stage-major pre-swizzled
__device__ float g_flatn[(size_t)NROWS * DDIM];
__device__ float g_embn[(size_t)KCB * DDIM];
__device__ float g_denx[NROWS];
__device__ float g_dene[KCB];
__device__ int   g_cand[(size_t)NROWS * 32];
__device__ float g_cval[(size_t)NROWS * 32];
__device__ int   g_ind[NROWS];
__device__ float g_bins[KCB];
__device__ float g_esum[(size_t)KCB * DDIM];

// ---------------- PTX helpers (all plain-sm_100-legal) ----------------
#define CP_ASYNC16(dst, src) \
    asm volatile("cp.async.cg.shared.global [%0], [%1], 16;" :: "r"(dst), "l"(src))
#define CP_COMMIT() asm volatile("cp.async.commit_group;" ::: "memory")
#define CP_WAIT0()  asm volatile("cp.async.wait_group 0;" ::: "memory")
#define BAR_SYNC(id, cnt) \
    asm volatile("bar.sync %0, %1;" :: "r"(id), "r"(cnt) : "memory")

__device__ __forceinline__ void ldsm4(uint32_t addr, uint32_t& r0, uint32_t& r1,
                                      uint32_t& r2, uint32_t& r3) {
    asm volatile("ldmatrix.sync.aligned.m8n8.x4.shared.b16 {%0,%1,%2,%3}, [%4];"
                 : "=r"(r0), "=r"(r1), "=r"(r2), "=r"(r3) : "r"(addr));
}

__device__ __forceinline__ void mma16816(float* c, const uint32_t* a, const uint32_t* b) {
    asm volatile("mma.sync.aligned.m16n8k16.row.col.f32.bf16.bf16.f32 "
                 "{%0,%1,%2,%3}, {%4,%5,%6,%7}, {%8,%9}, {%0,%1,%2,%3};"
                 : "+f"(c[0]), "+f"(c[1]), "+f"(c[2]), "+f"(c[3])
                 : "r"(a[0]), "r"(a[1]), "r"(a[2]), "r"(a[3]), "r"(b[0]), "r"(b[1]));
}

// ---------------- K0: normalize x rows -> g_flatn (fp32) + g_xB (bf16x2) ----------------
__global__ void k_norm_x(const float* __restrict__ x) {
    int w = (blockIdx.x * blockDim.x + threadIdx.x) >> 5;
    int lane = threadIdx.x & 31;
    if (w >= NROWS) return;
    const float2* x2 = (const float2*)x;
    float2 v[4];
    float s = 0.f;
#pragma unroll
    for (int i = 0; i < 4; i++) {
        v[i] = x2[(size_t)w * 128 + i * 32 + lane];
        s += v[i].x * v[i].x + v[i].y * v[i].y;
    }
#pragma unroll
    for (int off = 16; off >= 1; off >>= 1) s += __shfl_xor_sync(0xffffffffu, s, off);
    float den = fmaxf(__fsqrt_rn(s), 1e-12f);
#pragma unroll
    for (int i = 0; i < 4; i++) {
        int d2 = i * 32 + lane;
        float2 o;
        o.x = __fdiv_rn(v[i].x, den);
        o.y = __fdiv_rn(v[i].y, den);
        ((float2*)g_flatn)[(size_t)w * 128 + d2] = o;
        unsigned int u = ((unsigned int)__bfloat16_as_ushort(__float2bfloat16_rn(o.y)) << 16)
                       |  (unsigned int)__bfloat16_as_ushort(__float2bfloat16_rn(o.x));
        g_xB[(size_t)w * 128 + d2] = u;
    }
    if (lane == 0) g_denx[w] = den;
}

// ---------------- K1: normalize embed -> g_embn (fp32) + g_eBs (stage-major swizzled bf16) ----------------
// g_eBs layout: [block 32][stage 2][row 256][256B], chunk c (16B) stored at (c ^ (row&7))*16 + intra
__global__ void k_norm_e(const float* __restrict__ e) {
    int w = (blockIdx.x * blockDim.x + threadIdx.x) >> 5;
    int lane = threadIdx.x & 31;
    if (w >= KCB) return;
    const float2* e2 = (const float2*)e;
    float2 v[4];
    float s = 0.f;
#pragma unroll
    for (int i = 0; i < 4; i++) {
        v[i] = e2[(size_t)w * 128 + i * 32 + lane];
        s += v[i].x * v[i].x + v[i].y * v[i].y;
    }
#pragma unroll
    for (int off = 16; off >= 1; off >>= 1) s += __shfl_xor_sync(0xffffffffu, s, off);
    float den = fmaxf(__fsqrt_rn(s), 1e-12f);

    int blk = w >> 8, row = w & 255;
    size_t base = (size_t)blk * 131072 + (size_t)row * 256;
#pragma unroll
    for (int i = 0; i < 4; i++) {
        int d2 = i * 32 + lane;                 // pair index 0..127
        float2 o;
        o.x = __fdiv_rn(v[i].x, den);
        o.y = __fdiv_rn(v[i].y, den);
        ((float2*)g_embn)[(size_t)w * 128 + d2] = o;
        unsigned int u = ((unsigned int)__bfloat16_as_ushort(__float2bfloat16_rn(o.y)) << 16)
                       |  (unsigned int)__bfloat16_as_ushort(__float2bfloat16_rn(o.x));
        int stage = d2 >> 6;                    // k-half
        int d2s = d2 & 63;
        int c = d2s >> 2;                       // 16B chunk 0..15
        int intra = (d2s & 3) * 4;
        *(unsigned int*)(g_eBs + base + (size_t)stage * STAGE_BYTES
                         + (size_t)((c ^ (row & 7)) << 4) + intra) = u;
    }
    if (lane == 0) g_dene[w] = den;
}

// ---------------- K3: zero accumulators ----------------
__global__ void k_zero() {
    int i = blockIdx.x * blockDim.x + threadIdx.x;
    for (int j = i; j < KCB * DDIM; j += gridDim.x * blockDim.x) g_esum[j] = 0.f;
    if (i < KCB) g_bins[i] = 0.f;
}

// ---------------- K2: HMMA bf16 GEMM, 16 warps, 4 independent column-group pipelines ----------------
// smem: A (64KB, swizzled 512B rows) | group0 {buf0,buf1 16KB each} | group1 {...} | ...
__global__ void __launch_bounds__(512, 1) k_gemm_top2() {
    extern __shared__ unsigned char smem[];
    uint32_t sb = (uint32_t)__cvta_generic_to_shared(smem);
    uint32_t sA = sb;

    int tid = threadIdx.x;
    int lane = tid & 31;
    int wid = tid >> 5;
    int wm = wid >> 2;          // 0..3 (row 32-slab)
    int wn = wid & 3;           // 0..3 (column group)
    int gtid = wm * 32 + lane;  // 0..127 rank within column group
    int rowblk = blockIdx.x * BM;

    uint32_t sG = sb + A_BYTES + (uint32_t)wn * (2 * SLICE_BYTES);   // group's buffers

    // ---- stage A tile into smem (swizzled, 512B rows) ----
    {
        const char* srcA = (const char*)g_xB + (size_t)rowblk * 512;
#pragma unroll
        for (int q = 0; q < 8; q++) {
            int idx = tid + q * 512;
            int r = idx >> 5, c = idx & 31;
            uint32_t doff = (uint32_t)r * 512 + (uint32_t)((c ^ (r & 7)) << 4);
            CP_ASYNC16(sA + doff, srcA + (size_t)idx * 16);
        }
        CP_COMMIT();
    }
    // ---- prefetch group's B step 0 (linear: pre-swizzled in gmem) ----
    // group wn, step p = bb*2 + stage: src = g_eBs + bb*131072 + stage*65536 + wn*16384
    {
        const char* srcB = (const char*)g_eBs + (size_t)wn * SLICE_BYTES;
#pragma unroll
        for (int q = 0; q < 8; q++) {
            int idx = gtid + q * 128;
            CP_ASYNC16(sG + (uint32_t)idx * 16, srcB + (size_t)idx * 16);
        }
        CP_COMMIT();
    }
    CP_WAIT0();          // A + first B slice both landed for this thread
    __syncthreads();     // A visible to all

    // ---- fragment addressing ----
    int swz = lane & 7;
    int khalfA = lane >> 4;
    uint32_t aRowB[2];
#pragma unroll
    for (int mt = 0; mt < 2; mt++)
        aRowB[mt] = sA + (uint32_t)(wm * 32 + mt * 16 + (lane & 15)) * 512;
    int khalfB = (lane >> 3) & 1;
    uint32_t bRowOff[4];
#pragma unroll
    for (int ntp = 0; ntp < 4; ntp++)
        bRowOff[ntp] = (uint32_t)(ntp * 16 + (lane >> 4) * 8 + (lane & 7)) * 256;

    int barid = 1 + wn;

    // ---- per-thread top-2 per row (4 rows: mt*2 + h) ----
    float v1[4], v2[4];
    int   i1[4], i2[4];
#pragma unroll
    for (int s = 0; s < 4; s++) { v1[s] = -3.4e38f; v2[s] = -3.4e38f; i1[s] = 0; i2[s] = 0; }

    float acc[2][8][4];

    for (int p = 0; p < NSTEPS; p++) {
        int stage = p & 1;
        // data-ready barrier: all 4 warps of this group have their cp.async landed
        // (also serves as done-reading fence for the buffer the next prefetch targets)
        BAR_SYNC(barid, 128);

        // issue prefetch for step p+1 into buffer (p+1)&1 (read last at step p-1)
        if (p + 1 < NSTEPS) {
            int np = p + 1;
            const char* srcB = (const char*)g_eBs + (size_t)(np >> 1) * 131072
                             + (size_t)(np & 1) * STAGE_BYTES + (size_t)wn * SLICE_BYTES;
            uint32_t dst = sG + (uint32_t)((np & 1) ? SLICE_BYTES : 0);
#pragma unroll
            for (int q = 0; q < 8; q++) {
                int idx = gtid + q * 128;
                CP_ASYNC16(dst + (uint32_t)idx * 16, srcB + (size_t)idx * 16);
            }
            CP_COMMIT();
        }

        uint32_t sB = sG + (uint32_t)((p & 1) ? SLICE_BYTES : 0);

        if (stage == 0) {
#pragma unroll
            for (int mt = 0; mt < 2; mt++)
#pragma unroll
                for (int nt = 0; nt < 8; nt++)
#pragma unroll
                    for (int cc = 0; cc < 4; cc++) acc[mt][nt][cc] = 0.f;
        }

#pragma unroll
        for (int ks = 0; ks < 8; ks++) {
            uint32_t a[2][4];
            uint32_t offA = (uint32_t)(((stage * 16 + ks * 2 + khalfA) ^ swz) << 4);
#pragma unroll
            for (int mt = 0; mt < 2; mt++)
                ldsm4(aRowB[mt] + offA, a[mt][0], a[mt][1], a[mt][2], a[mt][3]);
            uint32_t b[8][2];
            uint32_t offB = (uint32_t)(((ks * 2 + khalfB) ^ swz) << 4);
#pragma unroll
            for (int ntp = 0; ntp < 4; ntp++) {
                uint32_t r0, r1, r2, r3;
                ldsm4(sB + bRowOff[ntp] + offB, r0, r1, r2, r3);
                b[ntp * 2][0] = r0; b[ntp * 2][1] = r1;
                b[ntp * 2 + 1][0] = r2; b[ntp * 2 + 1][1] = r3;
            }
#pragma unroll
            for (int mt = 0; mt < 2; mt++)
#pragma unroll
                for (int nt = 0; nt < 8; nt++)
                    mma16816(acc[mt][nt], a[mt], b[nt]);
        }

        // wait for the next step's data before looping (thread-local; barrier at loop top)
        if (p + 1 < NSTEPS) CP_WAIT0();

        if (stage == 1) {
            // epilogue: top-2 update over the 256-col block (k complete)
            int colq = (p >> 1) * BNBLK + wn * 64 + 2 * (lane & 3);
#pragma unroll
            for (int mt = 0; mt < 2; mt++) {
#pragma unroll
                for (int h = 0; h < 2; h++) {
                    int lr = mt * 2 + h;
#pragma unroll
                    for (int nt = 0; nt < 8; nt++) {
                        float va = acc[mt][nt][h * 2 + 0];
                        float vb = acc[mt][nt][h * 2 + 1];
                        if (fmaxf(va, vb) > v2[lr]) {
                            int c0 = colq + nt * 8;
                            if (va > v1[lr]) { v2[lr] = v1[lr]; i2[lr] = i1[lr]; v1[lr] = va; i1[lr] = c0; }
                            else if (va > v2[lr]) { v2[lr] = va; i2[lr] = c0; }
                            if (vb > v1[lr]) { v2[lr] = v1[lr]; i2[lr] = i1[lr]; v1[lr] = vb; i1[lr] = c0 + 1; }
                            else if (vb > v2[lr]) { v2[lr] = vb; i2[lr] = c0 + 1; }
                        }
                    }
                }
            }
        }
    }

    // write candidates: each row gets 32 slots = 16 buckets x 2
#pragma unroll
    for (int mt = 0; mt < 2; mt++) {
#pragma unroll
        for (int h = 0; h < 2; h++) {
            int lr = mt * 2 + h;
            int row = rowblk + wm * 32 + mt * 16 + (lane >> 2) + h * 8;
            int slot = (wn * 4 + (lane & 3)) * 2;
            g_cand[(size_t)row * 32 + slot]     = i1[lr];
            g_cand[(size_t)row * 32 + slot + 1] = i2[lr];
            g_cval[(size_t)row * 32 + slot]     = v1[lr];
            g_cval[(size_t)row * 32 + slot + 1] = v2[lr];
        }
    }
}

// ---------------- K2b: margin-gated exact fp32 rescore ----------------
__global__ void k_rescore() {
    int r = blockIdx.x * 8 + (threadIdx.x >> 5);
    int lane = threadIdx.x & 31;
    if (r >= NROWS) return;
    const float4* fr = (const float4*)(g_flatn + (size_t)r * DDIM);
    float4 fa = fr[lane * 2], fb = fr[lane * 2 + 1];

    float cv = g_cval[(size_t)r * 32 + lane];
    int   ci = g_cand[(size_t)r * 32 + lane];
    float wmax = cv;
#pragma unroll
    for (int off = 16; off >= 1; off >>= 1) wmax = fmaxf(wmax, __shfl_xor_sync(0xffffffffu, wmax, off));
    unsigned m = __ballot_sync(0xffffffffu, cv >= wmax - 2.5e-3f);

    float best = -3.4e38f;
    int besti = 0x7fffffff;
    while (m) {
        int b = __ffs(m) - 1;
        m &= m - 1;
        int cj = __shfl_sync(0xffffffffu, ci, b);
        const float4* er = (const float4*)(g_embn + (size_t)cj * DDIM);
        float4 ea = er[lane * 2], eb = er[lane * 2 + 1];
        float s = fa.x * ea.x + fa.y * ea.y + fa.z * ea.z + fa.w * ea.w
                + fb.x * eb.x + fb.y * eb.y + fb.z * eb.z + fb.w * eb.w;
#pragma unroll
        for (int off = 16; off >= 1; off >>= 1) s += __shfl_xor_sync(0xffffffffu, s, off);
        if (s > best || (s == best && cj < besti)) { best = s; besti = cj; }
    }
    if (lane == 0) g_ind[r] = besti;
}

// ---------------- K4: quantize gather + index out + segment-sum scatter ----------------
__global__ void k_scatter(const float* __restrict__ x, const float* __restrict__ embed,
                          float* __restrict__ out_q, float* __restrict__ out_ind) {
    int n = blockIdx.x;
    int t = threadIdx.x;
    int ind = g_ind[n];
    float den = g_denx[n];
    float fl = __fdiv_rn(x[(size_t)n * DDIM + t], den);
    atomicAdd(&g_esum[(size_t)ind * DDIM + t], fl);
    out_q[(size_t)n * DDIM + t] = embed[(size_t)ind * DDIM + t];
    if (t == 0) {
        atomicAdd(&g_bins[ind], 1.0f);
        out_ind[n] = (float)ind;
    }
}

// ---------------- K5: EMA finalize -> embed_new ----------------
__global__ void k_final(const float* __restrict__ embed, float* __restrict__ out_e) {
    int w = (blockIdx.x * blockDim.x + threadIdx.x) >> 5;
    int lane = threadIdx.x & 31;
    if (w >= KCB) return;
    float b = g_bins[w];
    bool zero = (b == 0.0f);
    float bs = zero ? 1.0f : b;
    float m[8];
    float s = 0.f;
#pragma unroll
    for (int i = 0; i < 8; i++) {
        int d = i * 32 + lane;
        m[i] = __fdiv_rn(g_esum[(size_t)w * DDIM + d], bs);
        s += m[i] * m[i];
    }
#pragma unroll
    for (int off = 16; off >= 1; off >>= 1) s += __shfl_xor_sync(0xffffffffu, s, off);
    float nrm = fmaxf(__fsqrt_rn(s), 1e-12f);
    float dene = g_dene[w];
#pragma unroll
    for (int i = 0; i < 8; i++) {
        int d = i * 32 + lane;
        float ev = embed[(size_t)w * DDIM + d];
        float en = zero ? __fdiv_rn(ev, dene) : __fdiv_rn(m[i], nrm);
        out_e[(size_t)w * DDIM + d] = ev * 0.8f + en * 0.2f;
    }
}

// ---------------- launcher ----------------
extern "C" void kernel_launch(void* const* d_in, const int* in_sizes, int n_in,
                              void* d_out, int out_size) {
    const float* x     = (const float*)d_in[0];
    const float* embed = (const float*)d_in[1];
    float* out     = (float*)d_out;
    float* out_q   = out;                          // [16384, 256]
    float* out_ind = out + (size_t)NROWS * DDIM;   // [16384]
    float* out_e   = out_ind + NROWS;              // [8192, 256]

    (void)in_sizes; (void)n_in; (void)out_size;

    const int smem_bytes = A_BYTES + 4 * 2 * SLICE_BYTES;   // 192 KB
    cudaFuncSetAttribute(k_gemm_top2, cudaFuncAttributeMaxDynamicSharedMemorySize, smem_bytes);

    k_norm_x<<<NROWS / 8, 256>>>(x);
    k_norm_e<<<KCB / 8, 256>>>(embed);
    k_zero<<<2048, 256>>>();
    k_gemm_top2<<<NROWS / BM, 512, smem_bytes>>>();
    k_rescore<<<NROWS / 8, 256>>>();
    k_scatter<<<NROWS, 256>>>(x, embed, out_q, out_ind);
    k_final<<<KCB / 8, 256>>>(embed, out_e);
}

// round 10
// speedup vs baseline: 1.3981x; 1.0882x over previous
#include <cuda_runtime.h>
#include <cuda_bf16.h>
#include <cstdint>
#include <cstddef>

#define NROWS 16384
#define KCB   8192
#define DDIM  256
#define BM    128
#define BNBLK 256                       // col-block per acc lifetime
#define NBLKS (KCB / BNBLK)             // 32
#define NSTEPS (NBLKS * 2)              // 64 (2 k-stages per block)
#define STAGE_BYTES 65536               // full 256-row x 128-k stage in gmem image
#define SLICE_BYTES 16384               // per-group 64-row x 128-k slice
#define A_BYTES  (BM * DDIM * 2)        // 65536

// ---------------- static device scratch ----------------
__device__ __align__(16) unsigned int g_xB[(size_t)NROWS * 128];    // x normalized, bf16x2 row-major [row][128]
__device__ __align__(16) unsigned char g_eBs[(size_t)KCB * 512];    // embed normalized bf16, stage-major pre-swizzled
__device__ float g_flatn[(size_t)NROWS * DDIM];
__device__ float g_embn[(size_t)KCB * DDIM];
__device__ float g_denx[NROWS];
__device__ float g_dene[KCB];
__device__ int   g_cand[(size_t)NROWS * 32];
__device__ float g_cval[(size_t)NROWS * 32];
__device__ int   g_ind[NROWS];
__device__ float g_bins[KCB];
__device__ float g_esum[(size_t)KCB * DDIM];

// ---------------- PTX helpers (all plain-sm_100-legal) ----------------
#define CP_ASYNC16(dst, src) \
    asm volatile("cp.async.cg.shared.global [%0], [%1], 16;" :: "r"(dst), "l"(src))
#define CP_COMMIT() asm volatile("cp.async.commit_group;" ::: "memory")
#define CP_WAIT0()  asm volatile("cp.async.wait_group 0;" ::: "memory")
#define BAR_SYNC(id, cnt) \
    asm volatile("bar.sync %0, %1;" :: "r"(id), "r"(cnt) : "memory")

__device__ __forceinline__ void ldsm4(uint32_t addr, uint32_t& r0, uint32_t& r1,
                                      uint32_t& r2, uint32_t& r3) {
    asm volatile("ldmatrix.sync.aligned.m8n8.x4.shared.b16 {%0,%1,%2,%3}, [%4];"
                 : "=r"(r0), "=r"(r1), "=r"(r2), "=r"(r3) : "r"(addr));
}

__device__ __forceinline__ void mma16816(float* c, const uint32_t* a, const uint32_t* b) {
    asm volatile("mma.sync.aligned.m16n8k16.row.col.f32.bf16.bf16.f32 "
                 "{%0,%1,%2,%3}, {%4,%5,%6,%7}, {%8,%9}, {%0,%1,%2,%3};"
                 : "+f"(c[0]), "+f"(c[1]), "+f"(c[2]), "+f"(c[3])
                 : "r"(a[0]), "r"(a[1]), "r"(a[2]), "r"(a[3]), "r"(b[0]), "r"(b[1]));
}

// ---------------- K0: normalize x rows -> g_flatn (fp32) + g_xB (bf16x2) ----------------
__global__ void k_norm_x(const float* __restrict__ x) {
    int w = (blockIdx.x * blockDim.x + threadIdx.x) >> 5;
    int lane = threadIdx.x & 31;
    if (w >= NROWS) return;
    const float2* x2 = (const float2*)x;
    float2 v[4];
    float s = 0.f;
#pragma unroll
    for (int i = 0; i < 4; i++) {
        v[i] = x2[(size_t)w * 128 + i * 32 + lane];
        s += v[i].x * v[i].x + v[i].y * v[i].y;
    }
#pragma unroll
    for (int off = 16; off >= 1; off >>= 1) s += __shfl_xor_sync(0xffffffffu, s, off);
    float den = fmaxf(__fsqrt_rn(s), 1e-12f);
#pragma unroll
    for (int i = 0; i < 4; i++) {
        int d2 = i * 32 + lane;
        float2 o;
        o.x = __fdiv_rn(v[i].x, den);
        o.y = __fdiv_rn(v[i].y, den);
        ((float2*)g_flatn)[(size_t)w * 128 + d2] = o;
        unsigned int u = ((unsigned int)__bfloat16_as_ushort(__float2bfloat16_rn(o.y)) << 16)
                       |  (unsigned int)__bfloat16_as_ushort(__float2bfloat16_rn(o.x));
        g_xB[(size_t)w * 128 + d2] = u;
    }
    if (lane == 0) g_denx[w] = den;
}

// ---------------- K1: normalize embed -> g_embn (fp32) + g_eBs (stage-major swizzled bf16) ----------------
// g_eBs layout: [block 32][stage 2][row 256][256B], chunk c (16B) stored at (c ^ (row&7))*16 + intra
__global__ void k_norm_e(const float* __restrict__ e) {
    int w = (blockIdx.x * blockDim.x + threadIdx.x) >> 5;
    int lane = threadIdx.x & 31;
    if (w >= KCB) return;
    const float2* e2 = (const float2*)e;
    float2 v[4];
    float s = 0.f;
#pragma unroll
    for (int i = 0; i < 4; i++) {
        v[i] = e2[(size_t)w * 128 + i * 32 + lane];
        s += v[i].x * v[i].x + v[i].y * v[i].y;
    }
#pragma unroll
    for (int off = 16; off >= 1; off >>= 1) s += __shfl_xor_sync(0xffffffffu, s, off);
    float den = fmaxf(__fsqrt_rn(s), 1e-12f);

    int blk = w >> 8, row = w & 255;
    size_t base = (size_t)blk * 131072 + (size_t)row * 256;
#pragma unroll
    for (int i = 0; i < 4; i++) {
        int d2 = i * 32 + lane;                 // pair index 0..127
        float2 o;
        o.x = __fdiv_rn(v[i].x, den);
        o.y = __fdiv_rn(v[i].y, den);
        ((float2*)g_embn)[(size_t)w * 128 + d2] = o;
        unsigned int u = ((unsigned int)__bfloat16_as_ushort(__float2bfloat16_rn(o.y)) << 16)
                       |  (unsigned int)__bfloat16_as_ushort(__float2bfloat16_rn(o.x));
        int stage = d2 >> 6;                    // k-half
        int d2s = d2 & 63;
        int c = d2s >> 2;                       // 16B chunk 0..15
        int intra = (d2s & 3) * 4;
        *(unsigned int*)(g_eBs + base + (size_t)stage * STAGE_BYTES
                         + (size_t)((c ^ (row & 7)) << 4) + intra) = u;
    }
    if (lane == 0) g_dene[w] = den;
}

// ---------------- K3: zero accumulators ----------------
__global__ void k_zero() {
    int i = blockIdx.x * blockDim.x + threadIdx.x;
    for (int j = i; j < KCB * DDIM; j += gridDim.x * blockDim.x) g_esum[j] = 0.f;
    if (i < KCB) g_bins[i] = 0.f;
}

// ---------------- K2: HMMA bf16 GEMM, 16 warps, 4 independent column-group pipelines ----------------
// Group-to-SMSP spread: wn = wid>>2 (group), wm = wid&3 (row slab) so each SMSP
// (wid&3) hosts one warp from EACH pipeline — a stalled group no longer idles a
// whole subpartition.
// smem: A (64KB, swizzled 512B rows) | group0 {buf0,buf1 16KB each} | group1 {...} | ...
__global__ void __launch_bounds__(512, 1) k_gemm_top2() {
    extern __shared__ unsigned char smem[];
    uint32_t sb = (uint32_t)__cvta_generic_to_shared(smem);
    uint32_t sA = sb;

    int tid = threadIdx.x;
    int lane = tid & 31;
    int wid = tid >> 5;
    int wn = wid >> 2;          // 0..3 (column group) — spread across SMSPs
    int wm = wid & 3;           // 0..3 (row 32-slab)
    int gtid = wm * 32 + lane;  // 0..127 rank within column group
    int rowblk = blockIdx.x * BM;

    uint32_t sG = sb + A_BYTES + (uint32_t)wn * (2 * SLICE_BYTES);   // group's buffers

    // ---- stage A tile into smem (swizzled, 512B rows) ----
    {
        const char* srcA = (const char*)g_xB + (size_t)rowblk * 512;
#pragma unroll
        for (int q = 0; q < 8; q++) {
            int idx = tid + q * 512;
            int r = idx >> 5, c = idx & 31;
            uint32_t doff = (uint32_t)r * 512 + (uint32_t)((c ^ (r & 7)) << 4);
            CP_ASYNC16(sA + doff, srcA + (size_t)idx * 16);
        }
        CP_COMMIT();
    }
    // ---- prefetch group's B step 0 (linear: pre-swizzled in gmem) ----
    {
        const char* srcB = (const char*)g_eBs + (size_t)wn * SLICE_BYTES;
#pragma unroll
        for (int q = 0; q < 8; q++) {
            int idx = gtid + q * 128;
            CP_ASYNC16(sG + (uint32_t)idx * 16, srcB + (size_t)idx * 16);
        }
        CP_COMMIT();
    }
    CP_WAIT0();          // A + first B slice both landed for this thread
    __syncthreads();     // A visible to all

    // ---- fragment addressing ----
    int swz = lane & 7;
    int khalfA = lane >> 4;
    uint32_t aRowB[2];
#pragma unroll
    for (int mt = 0; mt < 2; mt++)
        aRowB[mt] = sA + (uint32_t)(wm * 32 + mt * 16 + (lane & 15)) * 512;
    int khalfB = (lane >> 3) & 1;
    uint32_t bRowOff[4];
#pragma unroll
    for (int ntp = 0; ntp < 4; ntp++)
        bRowOff[ntp] = (uint32_t)(ntp * 16 + (lane >> 4) * 8 + (lane & 7)) * 256;

    int barid = 1 + wn;

    // ---- per-thread top-2 per row (4 rows: mt*2 + h) ----
    float v1[4], v2[4];
    int   i1[4], i2[4];
#pragma unroll
    for (int s = 0; s < 4; s++) { v1[s] = -3.4e38f; v2[s] = -3.4e38f; i1[s] = 0; i2[s] = 0; }

    float acc[2][8][4];

    for (int p = 0; p < NSTEPS; p++) {
        int stage = p & 1;
        // data-ready barrier: all 4 warps of this group have their cp.async landed
        // (also serves as done-reading fence for the buffer the next prefetch targets)
        BAR_SYNC(barid, 128);

        // issue prefetch for step p+1 into buffer (p+1)&1 (read last at step p-1)
        if (p + 1 < NSTEPS) {
            int np = p + 1;
            const char* srcB = (const char*)g_eBs + (size_t)(np >> 1) * 131072
                             + (size_t)(np & 1) * STAGE_BYTES + (size_t)wn * SLICE_BYTES;
            uint32_t dst = sG + (uint32_t)((np & 1) ? SLICE_BYTES : 0);
#pragma unroll
            for (int q = 0; q < 8; q++) {
                int idx = gtid + q * 128;
                CP_ASYNC16(dst + (uint32_t)idx * 16, srcB + (size_t)idx * 16);
            }
            CP_COMMIT();
        }

        uint32_t sB = sG + (uint32_t)((p & 1) ? SLICE_BYTES : 0);

        if (stage == 0) {
#pragma unroll
            for (int mt = 0; mt < 2; mt++)
#pragma unroll
                for (int nt = 0; nt < 8; nt++)
#pragma unroll
                    for (int cc = 0; cc < 4; cc++) acc[mt][nt][cc] = 0.f;
        }

#pragma unroll
        for (int ks = 0; ks < 8; ks++) {
            uint32_t a[2][4];
            uint32_t offA = (uint32_t)(((stage * 16 + ks * 2 + khalfA) ^ swz) << 4);
#pragma unroll
            for (int mt = 0; mt < 2; mt++)
                ldsm4(aRowB[mt] + offA, a[mt][0], a[mt][1], a[mt][2], a[mt][3]);
            uint32_t b[8][2];
            uint32_t offB = (uint32_t)(((ks * 2 + khalfB) ^ swz) << 4);
#pragma unroll
            for (int ntp = 0; ntp < 4; ntp++) {
                uint32_t r0, r1, r2, r3;
                ldsm4(sB + bRowOff[ntp] + offB, r0, r1, r2, r3);
                b[ntp * 2][0] = r0; b[ntp * 2][1] = r1;
                b[ntp * 2 + 1][0] = r2; b[ntp * 2 + 1][1] = r3;
            }
#pragma unroll
            for (int mt = 0; mt < 2; mt++)
#pragma unroll
                for (int nt = 0; nt < 8; nt++)
                    mma16816(acc[mt][nt], a[mt], b[nt]);
        }

        // wait for the next step's data before looping (thread-local; barrier at loop top)
        if (p + 1 < NSTEPS) CP_WAIT0();

        if (stage == 1) {
            // epilogue: top-2 update over the 256-col block (k complete)
            int colq = (p >> 1) * BNBLK + wn * 64 + 2 * (lane & 3);
#pragma unroll
            for (int mt = 0; mt < 2; mt++) {
#pragma unroll
                for (int h = 0; h < 2; h++) {
                    int lr = mt * 2 + h;
#pragma unroll
                    for (int nt = 0; nt < 8; nt++) {
                        float va = acc[mt][nt][h * 2 + 0];
                        float vb = acc[mt][nt][h * 2 + 1];
                        if (fmaxf(va, vb) > v2[lr]) {
                            int c0 = colq + nt * 8;
                            if (va > v1[lr]) { v2[lr] = v1[lr]; i2[lr] = i1[lr]; v1[lr] = va; i1[lr] = c0; }
                            else if (va > v2[lr]) { v2[lr] = va; i2[lr] = c0; }
                            if (vb > v1[lr]) { v2[lr] = v1[lr]; i2[lr] = i1[lr]; v1[lr] = vb; i1[lr] = c0 + 1; }
                            else if (vb > v2[lr]) { v2[lr] = vb; i2[lr] = c0 + 1; }
                        }
                    }
                }
            }
        }
    }

    // write candidates: each row gets 32 slots = 16 buckets x 2
#pragma unroll
    for (int mt = 0; mt < 2; mt++) {
#pragma unroll
        for (int h = 0; h < 2; h++) {
            int lr = mt * 2 + h;
            int row = rowblk + wm * 32 + mt * 16 + (lane >> 2) + h * 8;
            int slot = (wn * 4 + (lane & 3)) * 2;
            g_cand[(size_t)row * 32 + slot]     = i1[lr];
            g_cand[(size_t)row * 32 + slot + 1] = i2[lr];
            g_cval[(size_t)row * 32 + slot]     = v1[lr];
            g_cval[(size_t)row * 32 + slot + 1] = v2[lr];
        }
    }
}

// ---------------- K2b: margin-gated exact fp32 rescore ----------------
__global__ void k_rescore() {
    int r = blockIdx.x * 8 + (threadIdx.x >> 5);
    int lane = threadIdx.x & 31;
    if (r >= NROWS) return;
    const float4* fr = (const float4*)(g_flatn + (size_t)r * DDIM);
    float4 fa = fr[lane * 2], fb = fr[lane * 2 + 1];

    float cv = g_cval[(size_t)r * 32 + lane];
    int   ci = g_cand[(size_t)r * 32 + lane];
    float wmax = cv;
#pragma unroll
    for (int off = 16; off >= 1; off >>= 1) wmax = fmaxf(wmax, __shfl_xor_sync(0xffffffffu, wmax, off));
    unsigned m = __ballot_sync(0xffffffffu, cv >= wmax - 2.5e-3f);

    float best = -3.4e38f;
    int besti = 0x7fffffff;
    while (m) {
        int b = __ffs(m) - 1;
        m &= m - 1;
        int cj = __shfl_sync(0xffffffffu, ci, b);
        const float4* er = (const float4*)(g_embn + (size_t)cj * DDIM);
        float4 ea = er[lane * 2], eb = er[lane * 2 + 1];
        float s = fa.x * ea.x + fa.y * ea.y + fa.z * ea.z + fa.w * ea.w
                + fb.x * eb.x + fb.y * eb.y + fb.z * eb.z + fb.w * eb.w;
#pragma unroll
        for (int off = 16; off >= 1; off >>= 1) s += __shfl_xor_sync(0xffffffffu, s, off);
        if (s > best || (s == best && cj < besti)) { best = s; besti = cj; }
    }
    if (lane == 0) g_ind[r] = besti;
}

// ---------------- K4: quantize gather + index out + segment-sum scatter ----------------
__global__ void k_scatter(const float* __restrict__ x, const float* __restrict__ embed,
                          float* __restrict__ out_q, float* __restrict__ out_ind) {
    int n = blockIdx.x;
    int t = threadIdx.x;
    int ind = g_ind[n];
    float den = g_denx[n];
    float fl = __fdiv_rn(x[(size_t)n * DDIM + t], den);
    atomicAdd(&g_esum[(size_t)ind * DDIM + t], fl);
    out_q[(size_t)n * DDIM + t] = embed[(size_t)ind * DDIM + t];
    if (t == 0) {
        atomicAdd(&g_bins[ind], 1.0f);
        out_ind[n] = (float)ind;
    }
}

// ---------------- K5: EMA finalize -> embed_new ----------------
__global__ void k_final(const float* __restrict__ embed, float* __restrict__ out_e) {
    int w = (blockIdx.x * blockDim.x + threadIdx.x) >> 5;
    int lane = threadIdx.x & 31;
    if (w >= KCB) return;
    float b = g_bins[w];
    bool zero = (b == 0.0f);
    float bs = zero ? 1.0f : b;
    float m[8];
    float s = 0.f;
#pragma unroll
    for (int i = 0; i < 8; i++) {
        int d = i * 32 + lane;
        m[i] = __fdiv_rn(g_esum[(size_t)w * DDIM + d], bs);
        s += m[i] * m[i];
    }
#pragma unroll
    for (int off = 16; off >= 1; off >>= 1) s += __shfl_xor_sync(0xffffffffu, s, off);
    float nrm = fmaxf(__fsqrt_rn(s), 1e-12f);
    float dene = g_dene[w];
#pragma unroll
    for (int i = 0; i < 8; i++) {
        int d = i * 32 + lane;
        float ev = embed[(size_t)w * DDIM + d];
        float en = zero ? __fdiv_rn(ev, dene) : __fdiv_rn(m[i], nrm);
        out_e[(size_t)w * DDIM + d] = ev * 0.8f + en * 0.2f;
    }
}

// ---------------- launcher ----------------
extern "C" void kernel_launch(void* const* d_in, const int* in_sizes, int n_in,
                              void* d_out, int out_size) {
    const float* x     = (const float*)d_in[0];
    const float* embed = (const float*)d_in[1];
    float* out     = (float*)d_out;
    float* out_q   = out;                          // [16384, 256]
    float* out_ind = out + (size_t)NROWS * DDIM;   // [16384]
    float* out_e   = out_ind + NROWS;              // [8192, 256]

    (void)in_sizes; (void)n_in; (void)out_size;

    const int smem_bytes = A_BYTES + 4 * 2 * SLICE_BYTES;   // 192 KB
    cudaFuncSetAttribute(k_gemm_top2, cudaFuncAttributeMaxDynamicSharedMemorySize, smem_bytes);

    k_norm_x<<<NROWS / 8, 256>>>(x);
    k_norm_e<<<KCB / 8, 256>>>(embed);
    k_zero<<<2048, 256>>>();
    k_gemm_top2<<<NROWS / BM, 512, smem_bytes>>>();
    k_rescore<<<NROWS / 8, 256>>>();
    k_scatter<<<NROWS, 256>>>(x, embed, out_q, out_ind);
    k_final<<<KCB / 8, 256>>>(embed, out_e);
}